// round 1
// baseline (speedup 1.0000x reference)
#include <cuda_runtime.h>
#include <cstdint>

#define FULL 0xffffffffu

static constexpr int NN      = 50000;
static constexpr int NE      = 400000;
static constexpr int NODE_IN = 128;
static constexpr int F       = 256;   // HEADS*HID
static constexpr int HEADS   = 8;
static constexpr float SLOPE = 0.2f;

// ---------------- scratch (device globals; no allocation allowed) ----------------
__device__ float g_h[(size_t)NN * F];   // pre-aggregation node features (per layer)
__device__ float g_x[(size_t)NN * F];   // post-layer node features
__device__ float g_as[NN * HEADS];
__device__ float g_ad[NN * HEADS];
__device__ int   g_deg[NN];
__device__ int   g_off[NN + 1];
__device__ int   g_cur[NN];
__device__ int   g_col[NE];

__device__ __forceinline__ float lrelu(float x) { return x > 0.f ? x : SLOPE * x; }

// ---------------- CSR build ----------------
__global__ void k_zero(int* p, int n) {
    int i = blockIdx.x * blockDim.x + threadIdx.x;
    if (i < n) p[i] = 0;
}

__global__ void k_count(const int* __restrict__ ei) {
    int e = blockIdx.x * blockDim.x + threadIdx.x;
    if (e < NE) atomicAdd(&g_deg[ei[NE + e]], 1);
}

__global__ void k_scan() {   // single block, 1024 threads
    __shared__ int sh[32];
    __shared__ int s_carry;
    int tid = threadIdx.x;
    if (tid == 0) s_carry = 0;
    __syncthreads();
    for (int base = 0; base < NN; base += 1024) {
        int v = (base + tid < NN) ? g_deg[base + tid] : 0;
        int x = v;
        #pragma unroll
        for (int d = 1; d < 32; d <<= 1) {
            int y = __shfl_up_sync(FULL, x, d);
            if ((tid & 31) >= d) x += y;
        }
        if ((tid & 31) == 31) sh[tid >> 5] = x;
        __syncthreads();
        if (tid < 32) {
            int w = sh[tid];
            int wx = w;
            #pragma unroll
            for (int d = 1; d < 32; d <<= 1) {
                int y = __shfl_up_sync(FULL, wx, d);
                if (tid >= d) wx += y;
            }
            sh[tid] = wx - w;   // exclusive warp offset
        }
        __syncthreads();
        int incl = x + sh[tid >> 5];
        int excl = incl - v;
        int carry = s_carry;
        if (base + tid < NN) {
            g_off[base + tid] = carry + excl;
            g_cur[base + tid] = carry + excl;
        }
        __syncthreads();
        if (tid == 1023) s_carry = carry + incl;
        __syncthreads();
    }
    if (tid == 0) g_off[NN] = s_carry;
}

__global__ void k_fill(const int* __restrict__ ei) {
    int e = blockIdx.x * blockDim.x + threadIdx.x;
    if (e < NE) {
        int s = ei[e], d = ei[NE + e];
        int p = atomicAdd(&g_cur[d], 1);
        g_col[p] = s;
    }
}

// ---------------- fp32 GEMM: C[M,N] = A[M,K] @ B[K,N], row-major ----------------
// BM=128, BN=64, BK=16, 256 threads, TM=8, TN=4
__global__ __launch_bounds__(256) void k_gemm(const float* __restrict__ A,
                                              const float* __restrict__ B,
                                              float* __restrict__ C,
                                              int M, int N, int K) {
    __shared__ float As[16][128];
    __shared__ float Bs[16][64];
    int bm = blockIdx.y * 128, bn = blockIdx.x * 64;
    int tid = threadIdx.x;
    int tx = tid & 15, ty = tid >> 4;

    float acc[8][4];
    #pragma unroll
    for (int i = 0; i < 8; i++)
        #pragma unroll
        for (int j = 0; j < 4; j++) acc[i][j] = 0.f;

    for (int k0 = 0; k0 < K; k0 += 16) {
        #pragma unroll
        for (int t = 0; t < 2; t++) {
            int f = tid + t * 256;
            int r = f >> 2, c4 = (f & 3) * 4;
            int grow = bm + r;
            if (grow >= M) grow = M - 1;
            float4 v = *(const float4*)&A[(size_t)grow * K + k0 + c4];
            As[c4 + 0][r] = v.x; As[c4 + 1][r] = v.y;
            As[c4 + 2][r] = v.z; As[c4 + 3][r] = v.w;
        }
        {
            int r = tid >> 4, c4 = (tid & 15) * 4;
            *(float4*)&Bs[r][c4] = *(const float4*)&B[(size_t)(k0 + r) * N + bn + c4];
        }
        __syncthreads();
        #pragma unroll
        for (int k = 0; k < 16; k++) {
            float4 a0 = *(const float4*)&As[k][ty * 8];
            float4 a1 = *(const float4*)&As[k][ty * 8 + 4];
            float4 bb = *(const float4*)&Bs[k][tx * 4];
            float a[8] = {a0.x, a0.y, a0.z, a0.w, a1.x, a1.y, a1.z, a1.w};
            float b[4] = {bb.x, bb.y, bb.z, bb.w};
            #pragma unroll
            for (int i = 0; i < 8; i++)
                #pragma unroll
                for (int j = 0; j < 4; j++)
                    acc[i][j] = fmaf(a[i], b[j], acc[i][j]);
        }
        __syncthreads();
    }
    #pragma unroll
    for (int i = 0; i < 8; i++) {
        int grow = bm + ty * 8 + i;
        if (grow < M) {
            float4 o = make_float4(acc[i][0], acc[i][1], acc[i][2], acc[i][3]);
            *(float4*)&C[(size_t)grow * N + bn + tx * 4] = o;
        }
    }
}

// ---------------- attention coefficients: as[n,h], ad[n,h] ----------------
__global__ void k_attn(const float* __restrict__ h, const float* __restrict__ a_src,
                       const float* __restrict__ a_dst) {
    int warp = (blockIdx.x * blockDim.x + threadIdx.x) >> 5;
    int lane = threadIdx.x & 31;
    if (warp >= NN) return;
    int head = lane >> 2, part = lane & 3;
    const float4* hp = (const float4*)(h + (size_t)warp * F + head * 32 + part * 8);
    const float4* ap = (const float4*)(a_src + head * 32 + part * 8);
    const float4* dp = (const float4*)(a_dst + head * 32 + part * 8);
    float4 h0 = hp[0], h1 = hp[1];
    float4 a0 = ap[0], a1 = ap[1];
    float4 d0 = dp[0], d1 = dp[1];
    float s = h0.x * a0.x + h0.y * a0.y + h0.z * a0.z + h0.w * a0.w
            + h1.x * a1.x + h1.y * a1.y + h1.z * a1.z + h1.w * a1.w;
    float d = h0.x * d0.x + h0.y * d0.y + h0.z * d0.z + h0.w * d0.w
            + h1.x * d1.x + h1.y * d1.y + h1.z * d1.z + h1.w * d1.w;
    s += __shfl_xor_sync(FULL, s, 1); s += __shfl_xor_sync(FULL, s, 2);
    d += __shfl_xor_sync(FULL, d, 1); d += __shfl_xor_sync(FULL, d, 2);
    if (part == 0) {
        g_as[warp * HEADS + head] = s;
        g_ad[warp * HEADS + head] = d;
    }
}

// ---------------- GAT segment-softmax aggregation (warp per node) ----------------
__global__ void k_agg(const float* __restrict__ h, const float* __restrict__ bias,
                      float* __restrict__ out) {
    int n = (blockIdx.x * blockDim.x + threadIdx.x) >> 5;
    int lane = threadIdx.x & 31;
    if (n >= NN) return;
    int head = lane >> 2, part = lane & 3;

    float adv = g_ad[n * HEADS + head];
    float e_self = lrelu(g_as[n * HEADS + head] + adv);
    int beg = g_off[n], end = g_off[n + 1];

    // pass 1: segment max (self-loop included)
    float m = e_self;
    for (int i = beg; i < end; i++) {
        int s = g_col[i];
        m = fmaxf(m, lrelu(g_as[s * HEADS + head] + adv));
    }

    // pass 2: exp-sum + weighted aggregate
    float w = __expf(e_self - m);
    float denom = w;
    const float4* hp = (const float4*)(h + (size_t)n * F + head * 32 + part * 8);
    float4 v0 = hp[0], v1 = hp[1];
    float4 acc0 = make_float4(w * v0.x, w * v0.y, w * v0.z, w * v0.w);
    float4 acc1 = make_float4(w * v1.x, w * v1.y, w * v1.z, w * v1.w);
    for (int i = beg; i < end; i++) {
        int s = g_col[i];
        float ww = __expf(lrelu(g_as[s * HEADS + head] + adv) - m);
        denom += ww;
        const float4* sp = (const float4*)(h + (size_t)s * F + head * 32 + part * 8);
        float4 s0 = sp[0], s1 = sp[1];
        acc0.x = fmaf(ww, s0.x, acc0.x); acc0.y = fmaf(ww, s0.y, acc0.y);
        acc0.z = fmaf(ww, s0.z, acc0.z); acc0.w = fmaf(ww, s0.w, acc0.w);
        acc1.x = fmaf(ww, s1.x, acc1.x); acc1.y = fmaf(ww, s1.y, acc1.y);
        acc1.z = fmaf(ww, s1.z, acc1.z); acc1.w = fmaf(ww, s1.w, acc1.w);
    }
    float inv = 1.f / denom;
    const float4* bp = (const float4*)(bias + head * 32 + part * 8);
    float4 b0 = bp[0], b1 = bp[1];
    float4 o0, o1;
    o0.x = fmaxf(fmaf(acc0.x, inv, b0.x), 0.f);
    o0.y = fmaxf(fmaf(acc0.y, inv, b0.y), 0.f);
    o0.z = fmaxf(fmaf(acc0.z, inv, b0.z), 0.f);
    o0.w = fmaxf(fmaf(acc0.w, inv, b0.w), 0.f);
    o1.x = fmaxf(fmaf(acc1.x, inv, b1.x), 0.f);
    o1.y = fmaxf(fmaf(acc1.y, inv, b1.y), 0.f);
    o1.z = fmaxf(fmaf(acc1.z, inv, b1.z), 0.f);
    o1.w = fmaxf(fmaf(acc1.w, inv, b1.w), 0.f);
    float4* op = (float4*)(out + (size_t)n * F + head * 32 + part * 8);
    op[0] = o0; op[1] = o1;
}

// ---------------- fused edge-MLP + predictor ----------------
// 4 warps / block, each warp processes 4 edges per sweep.
// smem: Wp1T[32][548] | Wm1[1024] | Wm2[1024] | consts[132] | ef[4 warps][4 edges][548]
static constexpr int EF_PAD = 548;
static constexpr int SM_WP1T = 32 * EF_PAD;                 // 17536
static constexpr int SM_WM1  = SM_WP1T + 1024;              // after Wp1T
static constexpr int SM_CST  = SM_WM1 + 1024;               // Wm2 lives at SM_WM1..; consts after
static constexpr int SM_EF   = SM_CST + 1024 + 132;         // careful layout below

__global__ __launch_bounds__(128) void k_pred(const int* __restrict__ EI,
                                              const float* __restrict__ EA,
                                              const float* __restrict__ X,
                                              const float* __restrict__ Wm1,
                                              const float* __restrict__ bm1,
                                              const float* __restrict__ Wm2,
                                              const float* __restrict__ bm2,
                                              const float* __restrict__ Wp1,
                                              const float* __restrict__ bp1,
                                              const float* __restrict__ Wp2,
                                              const float* __restrict__ bp2,
                                              float* __restrict__ OUT) {
    extern __shared__ float sm[];
    float* sWp1T = sm;                       // 32*548
    float* sWm1  = sWp1T + 32 * EF_PAD;      // 1024
    float* sWm2  = sWm1 + 1024;              // 1024
    float* sCst  = sWm2 + 1024;              // bm1[32] bm2[32] bp1[32] Wp2[32] bp2[1] pad->132
    float* sEf   = sCst + 132;               // 16 * 548

    int tid = threadIdx.x;
    for (int i = tid; i < 544 * 32; i += 128)
        sWp1T[(i & 31) * EF_PAD + (i >> 5)] = Wp1[i];
    for (int i = tid; i < 1024; i += 128) { sWm1[i] = Wm1[i]; sWm2[i] = Wm2[i]; }
    if (tid < 32) {
        sCst[tid]       = bm1[tid];
        sCst[32 + tid]  = bm2[tid];
        sCst[64 + tid]  = bp1[tid];
        sCst[96 + tid]  = Wp2[tid];
    }
    if (tid == 0) sCst[128] = bp2[0];
    __syncthreads();

    int warpId = tid >> 5, lane = tid & 31;
    float* myEf = sEf + warpId * 4 * EF_PAD;

    for (int base = blockIdx.x * 16; base < NE; base += gridDim.x * 16) {
        int e0 = base + warpId * 4;
        // stage ef for 4 edges
        #pragma unroll
        for (int q = 0; q < 4; q++) {
            int e = e0 + q;
            int ec = (e < NE) ? e : NE - 1;
            int r = EI[ec], c = EI[NE + ec];
            float* efq = myEf + q * EF_PAD;
            const float4* xr = (const float4*)(X + (size_t)r * F);
            const float4* xc = (const float4*)(X + (size_t)c * F);
            ((float4*)efq)[lane]      = xr[lane];
            ((float4*)efq)[32 + lane] = xr[32 + lane];
            ((float4*)efq)[64 + lane] = xc[lane];
            ((float4*)efq)[96 + lane] = xc[32 + lane];
            // edge MLP
            float ea = EA[(size_t)ec * 32 + lane];
            float tv = sCst[lane];
            #pragma unroll
            for (int k = 0; k < 32; k++)
                tv = fmaf(__shfl_sync(FULL, ea, k), sWm1[k * 32 + lane], tv);
            tv = fmaxf(tv, 0.f);
            float uv = sCst[32 + lane];
            #pragma unroll
            for (int k = 0; k < 32; k++)
                uv = fmaf(__shfl_sync(FULL, tv, k), sWm2[k * 32 + lane], uv);
            efq[512 + lane] = fmaxf(uv, 0.f);
        }
        __syncwarp();

        float4 acc[4];
        #pragma unroll
        for (int q = 0; q < 4; q++) acc[q] = make_float4(0.f, 0.f, 0.f, 0.f);
        const float4* wrow = (const float4*)(sWp1T + lane * EF_PAD);
        #pragma unroll 4
        for (int k4 = 0; k4 < 136; k4++) {
            float4 wv = wrow[k4];
            #pragma unroll
            for (int q = 0; q < 4; q++) {
                float4 ev = ((const float4*)(myEf + q * EF_PAD))[k4];
                acc[q].x = fmaf(ev.x, wv.x, acc[q].x);
                acc[q].y = fmaf(ev.y, wv.y, acc[q].y);
                acc[q].z = fmaf(ev.z, wv.z, acc[q].z);
                acc[q].w = fmaf(ev.w, wv.w, acc[q].w);
            }
        }
        #pragma unroll
        for (int q = 0; q < 4; q++) {
            float hid = acc[q].x + acc[q].y + acc[q].z + acc[q].w + sCst[64 + lane];
            hid = fmaxf(hid, 0.f);
            float p = hid * sCst[96 + lane];
            #pragma unroll
            for (int d = 16; d; d >>= 1) p += __shfl_xor_sync(FULL, p, d);
            if (lane == 0 && e0 + q < NE) OUT[e0 + q] = p + sCst[128];
        }
        __syncwarp();
    }
}

// ---------------- launch ----------------
extern "C" void kernel_launch(void* const* d_in, const int* in_sizes, int n_in,
                              void* d_out, int out_size) {
    const float* x    = (const float*)d_in[0];
    const int*   ei   = (const int*)d_in[1];
    const float* ea   = (const float*)d_in[2];
    const float* W1   = (const float*)d_in[3];
    const float* as1  = (const float*)d_in[4];
    const float* ad1  = (const float*)d_in[5];
    const float* b1   = (const float*)d_in[6];
    const float* W2   = (const float*)d_in[7];
    const float* as2  = (const float*)d_in[8];
    const float* ad2  = (const float*)d_in[9];
    const float* b2   = (const float*)d_in[10];
    const float* Wm1  = (const float*)d_in[11];
    const float* bm1  = (const float*)d_in[12];
    const float* Wm2  = (const float*)d_in[13];
    const float* bm2  = (const float*)d_in[14];
    const float* Wp1  = (const float*)d_in[15];
    const float* bp1  = (const float*)d_in[16];
    const float* Wp2  = (const float*)d_in[17];
    const float* bp2  = (const float*)d_in[18];
    float* out = (float*)d_out;

    float *ph, *px, *pas, *pad;
    int *pdeg, *pcol;
    cudaGetSymbolAddress((void**)&ph,  g_h);
    cudaGetSymbolAddress((void**)&px,  g_x);
    (void)pas; (void)pad; (void)pdeg; (void)pcol; // kernels use globals directly

    // CSR
    {
        int* degp; cudaGetSymbolAddress((void**)&degp, g_deg);
        k_zero<<<(NN + 255) / 256, 256>>>(degp, NN);
    }
    k_count<<<(NE + 255) / 256, 256>>>(ei);
    k_scan<<<1, 1024>>>();
    k_fill<<<(NE + 255) / 256, 256>>>(ei);

    dim3 ggrid(F / 64, (NN + 127) / 128);
    int nwBlocks = (NN * 32 + 255) / 256;

    // layer 1
    k_gemm<<<ggrid, 256>>>(x, W1, ph, NN, F, NODE_IN);
    k_attn<<<nwBlocks, 256>>>(ph, as1, ad1);
    k_agg<<<nwBlocks, 256>>>(ph, b1, px);

    // layer 2
    k_gemm<<<ggrid, 256>>>(px, W2, ph, NN, F, F);
    k_attn<<<nwBlocks, 256>>>(ph, as2, ad2);
    k_agg<<<nwBlocks, 256>>>(ph, b2, px);

    // fused edge MLP + predictor
    size_t smBytes = (size_t)(32 * EF_PAD + 1024 + 1024 + 132 + 16 * EF_PAD) * sizeof(float);
    cudaFuncSetAttribute(k_pred, cudaFuncAttributeMaxDynamicSharedMemorySize, (int)smBytes);
    k_pred<<<304, 128, smBytes>>>(ei, ea, px, Wm1, bm1, Wm2, bm2,
                                  Wp1, bp1, Wp2, bp2, out);
}

// round 3
// speedup vs baseline: 1.9472x; 1.9472x over previous
#include <cuda_runtime.h>
#include <cstdint>

#define FULL 0xffffffffu

static constexpr int NN      = 50000;
static constexpr int NE      = 400000;
static constexpr int NODE_IN = 128;
static constexpr int F       = 256;   // HEADS*HID
static constexpr int HEADS   = 8;
static constexpr float SLOPE = 0.2f;

// ---------------- scratch (device globals; no allocation allowed) ----------------
__device__ float g_h[(size_t)NN * F];   // pre-aggregation node features (per layer)
__device__ float g_x[(size_t)NN * F];   // post-layer node features
__device__ float g_P[(size_t)NN * 64];  // per-node predictor partials: [Pa | Pb]
__device__ float g_Wpab[256 * 64];      // packed [Wp1_a | Wp1_b] as [256,64]
__device__ float g_as[NN * HEADS];
__device__ float g_ad[NN * HEADS];
__device__ int   g_deg[NN];
__device__ int   g_off[NN + 1];
__device__ int   g_cur[NN];
__device__ int   g_col[NE];

__device__ __forceinline__ float lrelu(float x) { return x > 0.f ? x : SLOPE * x; }

// ---------------- CSR build ----------------
__global__ void k_zero(int* p, int n) {
    int i = blockIdx.x * blockDim.x + threadIdx.x;
    if (i < n) p[i] = 0;
}

__global__ void k_count(const int* __restrict__ ei) {
    int e = blockIdx.x * blockDim.x + threadIdx.x;
    if (e < NE) atomicAdd(&g_deg[ei[NE + e]], 1);
}

__global__ void k_scan() {   // single block, 1024 threads
    __shared__ int sh[32];
    __shared__ int s_carry;
    int tid = threadIdx.x;
    if (tid == 0) s_carry = 0;
    __syncthreads();
    for (int base = 0; base < NN; base += 1024) {
        int v = (base + tid < NN) ? g_deg[base + tid] : 0;
        int x = v;
        #pragma unroll
        for (int d = 1; d < 32; d <<= 1) {
            int y = __shfl_up_sync(FULL, x, d);
            if ((tid & 31) >= d) x += y;
        }
        if ((tid & 31) == 31) sh[tid >> 5] = x;
        __syncthreads();
        if (tid < 32) {
            int w = sh[tid];
            int wx = w;
            #pragma unroll
            for (int d = 1; d < 32; d <<= 1) {
                int y = __shfl_up_sync(FULL, wx, d);
                if (tid >= d) wx += y;
            }
            sh[tid] = wx - w;   // exclusive warp offset
        }
        __syncthreads();
        int incl = x + sh[tid >> 5];
        int excl = incl - v;
        int carry = s_carry;
        if (base + tid < NN) {
            g_off[base + tid] = carry + excl;
            g_cur[base + tid] = carry + excl;
        }
        __syncthreads();
        if (tid == 1023) s_carry = carry + incl;
        __syncthreads();
    }
    if (tid == 0) g_off[NN] = s_carry;
}

__global__ void k_fill(const int* __restrict__ ei) {
    int e = blockIdx.x * blockDim.x + threadIdx.x;
    if (e < NE) {
        int s = ei[e], d = ei[NE + e];
        int p = atomicAdd(&g_cur[d], 1);
        g_col[p] = s;
    }
}

// ---------------- fp32 GEMM (BN=64 variant, used for the P GEMM) ----------------
__global__ __launch_bounds__(256) void k_gemm(const float* __restrict__ A,
                                              const float* __restrict__ B,
                                              float* __restrict__ C,
                                              int M, int N, int K) {
    __shared__ float As[16][128];
    __shared__ float Bs[16][64];
    int bm = blockIdx.y * 128, bn = blockIdx.x * 64;
    int tid = threadIdx.x;
    int tx = tid & 15, ty = tid >> 4;

    float acc[8][4];
    #pragma unroll
    for (int i = 0; i < 8; i++)
        #pragma unroll
        for (int j = 0; j < 4; j++) acc[i][j] = 0.f;

    for (int k0 = 0; k0 < K; k0 += 16) {
        #pragma unroll
        for (int t = 0; t < 2; t++) {
            int f = tid + t * 256;
            int r = f >> 2, c4 = (f & 3) * 4;
            int grow = bm + r;
            if (grow >= M) grow = M - 1;
            float4 v = *(const float4*)&A[(size_t)grow * K + k0 + c4];
            As[c4 + 0][r] = v.x; As[c4 + 1][r] = v.y;
            As[c4 + 2][r] = v.z; As[c4 + 3][r] = v.w;
        }
        {
            int r = tid >> 4, c4 = (tid & 15) * 4;
            *(float4*)&Bs[r][c4] = *(const float4*)&B[(size_t)(k0 + r) * N + bn + c4];
        }
        __syncthreads();
        #pragma unroll
        for (int k = 0; k < 16; k++) {
            float4 a0 = *(const float4*)&As[k][ty * 8];
            float4 a1 = *(const float4*)&As[k][ty * 8 + 4];
            float4 bb = *(const float4*)&Bs[k][tx * 4];
            float a[8] = {a0.x, a0.y, a0.z, a0.w, a1.x, a1.y, a1.z, a1.w};
            float b[4] = {bb.x, bb.y, bb.z, bb.w};
            #pragma unroll
            for (int i = 0; i < 8; i++)
                #pragma unroll
                for (int j = 0; j < 4; j++)
                    acc[i][j] = fmaf(a[i], b[j], acc[i][j]);
        }
        __syncthreads();
    }
    #pragma unroll
    for (int i = 0; i < 8; i++) {
        int grow = bm + ty * 8 + i;
        if (grow < M) {
            float4 o = make_float4(acc[i][0], acc[i][1], acc[i][2], acc[i][3]);
            *(float4*)&C[(size_t)grow * N + bn + tx * 4] = o;
        }
    }
}

// ---------------- fp32 GEMM 128x128, BK=8, TM=8, TN=8 (node GEMMs) ----------------
__global__ __launch_bounds__(256) void k_gemm128(const float* __restrict__ A,
                                                 const float* __restrict__ B,
                                                 float* __restrict__ C,
                                                 int M, int N, int K) {
    __shared__ float As[8][128];
    __shared__ float Bs[8][128];
    int bm = blockIdx.y * 128, bn = blockIdx.x * 128;
    int tid = threadIdx.x;
    int tx = tid & 15, ty = tid >> 4;   // 16x16 thread grid

    float acc[8][8];
    #pragma unroll
    for (int i = 0; i < 8; i++)
        #pragma unroll
        for (int j = 0; j < 8; j++) acc[i][j] = 0.f;

    for (int k0 = 0; k0 < K; k0 += 8) {
        {   // A tile: 128 rows x 8 cols; thread loads one float4
            int r = tid >> 1, c4 = (tid & 1) * 4;
            int grow = bm + r;
            if (grow >= M) grow = M - 1;
            float4 v = *(const float4*)&A[(size_t)grow * K + k0 + c4];
            As[c4 + 0][r] = v.x; As[c4 + 1][r] = v.y;
            As[c4 + 2][r] = v.z; As[c4 + 3][r] = v.w;
        }
        {   // B tile: 8 rows x 128 cols
            int r = tid >> 5, c4 = (tid & 31) * 4;
            *(float4*)&Bs[r][c4] = *(const float4*)&B[(size_t)(k0 + r) * N + bn + c4];
        }
        __syncthreads();
        #pragma unroll
        for (int k = 0; k < 8; k++) {
            float4 a0 = *(const float4*)&As[k][ty * 8];
            float4 a1 = *(const float4*)&As[k][ty * 8 + 4];
            float4 b0 = *(const float4*)&Bs[k][tx * 8];
            float4 b1 = *(const float4*)&Bs[k][tx * 8 + 4];
            float a[8] = {a0.x, a0.y, a0.z, a0.w, a1.x, a1.y, a1.z, a1.w};
            float b[8] = {b0.x, b0.y, b0.z, b0.w, b1.x, b1.y, b1.z, b1.w};
            #pragma unroll
            for (int i = 0; i < 8; i++)
                #pragma unroll
                for (int j = 0; j < 8; j++)
                    acc[i][j] = fmaf(a[i], b[j], acc[i][j]);
        }
        __syncthreads();
    }
    #pragma unroll
    for (int i = 0; i < 8; i++) {
        int grow = bm + ty * 8 + i;
        if (grow < M) {
            float4 o0 = make_float4(acc[i][0], acc[i][1], acc[i][2], acc[i][3]);
            float4 o1 = make_float4(acc[i][4], acc[i][5], acc[i][6], acc[i][7]);
            *(float4*)&C[(size_t)grow * N + bn + tx * 8]     = o0;
            *(float4*)&C[(size_t)grow * N + bn + tx * 8 + 4] = o1;
        }
    }
}

// ---------------- attention coefficients: as[n,h], ad[n,h] ----------------
__global__ void k_attn(const float* __restrict__ h, const float* __restrict__ a_src,
                       const float* __restrict__ a_dst) {
    int warp = (blockIdx.x * blockDim.x + threadIdx.x) >> 5;
    int lane = threadIdx.x & 31;
    if (warp >= NN) return;
    int head = lane >> 2, part = lane & 3;
    const float4* hp = (const float4*)(h + (size_t)warp * F + head * 32 + part * 8);
    const float4* ap = (const float4*)(a_src + head * 32 + part * 8);
    const float4* dp = (const float4*)(a_dst + head * 32 + part * 8);
    float4 h0 = hp[0], h1 = hp[1];
    float4 a0 = ap[0], a1 = ap[1];
    float4 d0 = dp[0], d1 = dp[1];
    float s = h0.x * a0.x + h0.y * a0.y + h0.z * a0.z + h0.w * a0.w
            + h1.x * a1.x + h1.y * a1.y + h1.z * a1.z + h1.w * a1.w;
    float d = h0.x * d0.x + h0.y * d0.y + h0.z * d0.z + h0.w * d0.w
            + h1.x * d1.x + h1.y * d1.y + h1.z * d1.z + h1.w * d1.w;
    s += __shfl_xor_sync(FULL, s, 1); s += __shfl_xor_sync(FULL, s, 2);
    d += __shfl_xor_sync(FULL, d, 1); d += __shfl_xor_sync(FULL, d, 2);
    if (part == 0) {
        g_as[warp * HEADS + head] = s;
        g_ad[warp * HEADS + head] = d;
    }
}

// ---------------- GAT segment-softmax aggregation (warp per node) ----------------
__global__ void k_agg(const float* __restrict__ h, const float* __restrict__ bias,
                      float* __restrict__ out) {
    int n = (blockIdx.x * blockDim.x + threadIdx.x) >> 5;
    int lane = threadIdx.x & 31;
    if (n >= NN) return;
    int head = lane >> 2, part = lane & 3;

    float adv = g_ad[n * HEADS + head];
    float e_self = lrelu(g_as[n * HEADS + head] + adv);
    int beg = g_off[n], end = g_off[n + 1];

    float m = e_self;
    for (int i = beg; i < end; i++) {
        int s = g_col[i];
        m = fmaxf(m, lrelu(g_as[s * HEADS + head] + adv));
    }

    float w = __expf(e_self - m);
    float denom = w;
    const float4* hp = (const float4*)(h + (size_t)n * F + head * 32 + part * 8);
    float4 v0 = hp[0], v1 = hp[1];
    float4 acc0 = make_float4(w * v0.x, w * v0.y, w * v0.z, w * v0.w);
    float4 acc1 = make_float4(w * v1.x, w * v1.y, w * v1.z, w * v1.w);
    for (int i = beg; i < end; i++) {
        int s = g_col[i];
        float ww = __expf(lrelu(g_as[s * HEADS + head] + adv) - m);
        denom += ww;
        const float4* sp = (const float4*)(h + (size_t)s * F + head * 32 + part * 8);
        float4 s0 = sp[0], s1 = sp[1];
        acc0.x = fmaf(ww, s0.x, acc0.x); acc0.y = fmaf(ww, s0.y, acc0.y);
        acc0.z = fmaf(ww, s0.z, acc0.z); acc0.w = fmaf(ww, s0.w, acc0.w);
        acc1.x = fmaf(ww, s1.x, acc1.x); acc1.y = fmaf(ww, s1.y, acc1.y);
        acc1.z = fmaf(ww, s1.z, acc1.z); acc1.w = fmaf(ww, s1.w, acc1.w);
    }
    float inv = 1.f / denom;
    const float4* bp = (const float4*)(bias + head * 32 + part * 8);
    float4 b0 = bp[0], b1 = bp[1];
    float4 o0, o1;
    o0.x = fmaxf(fmaf(acc0.x, inv, b0.x), 0.f);
    o0.y = fmaxf(fmaf(acc0.y, inv, b0.y), 0.f);
    o0.z = fmaxf(fmaf(acc0.z, inv, b0.z), 0.f);
    o0.w = fmaxf(fmaf(acc0.w, inv, b0.w), 0.f);
    o1.x = fmaxf(fmaf(acc1.x, inv, b1.x), 0.f);
    o1.y = fmaxf(fmaf(acc1.y, inv, b1.y), 0.f);
    o1.z = fmaxf(fmaf(acc1.z, inv, b1.z), 0.f);
    o1.w = fmaxf(fmaf(acc1.w, inv, b1.w), 0.f);
    float4* op = (float4*)(out + (size_t)n * F + head * 32 + part * 8);
    op[0] = o0; op[1] = o1;
}

// ---------------- pack [Wp1_a | Wp1_b] into [256,64] ----------------
__global__ void k_packWp1(const float* __restrict__ Wp1) {
    int i = blockIdx.x * blockDim.x + threadIdx.x;
    if (i < 256 * 64) {
        int k = i >> 6, j = i & 63;
        g_Wpab[i] = (j < 32) ? Wp1[k * 32 + j] : Wp1[(256 + k) * 32 + (j - 32)];
    }
}

// ---------------- edge predictor: thread per edge ----------------
// hid = relu( emb@Wp1c + Pa[row] + Pb[col] + bp1 ), out = hid@Wp2 + bp2
// where emb = relu(relu(ea@Wm1+bm1)@Wm2+bm2).
// All three 32x32 matmuls share one unrolled body (L-loop, no unroll).
__global__ __launch_bounds__(256) void k_pred(const int* __restrict__ EI,
                                              const float* __restrict__ EA,
                                              const float* __restrict__ Wm1,
                                              const float* __restrict__ bm1,
                                              const float* __restrict__ Wm2,
                                              const float* __restrict__ bm2,
                                              const float* __restrict__ Wp1,
                                              const float* __restrict__ bp1,
                                              const float* __restrict__ Wp2,
                                              const float* __restrict__ bp2,
                                              float* __restrict__ OUT) {
    __shared__ float sW[3 * 1024];   // [L][k][j]: Wm1, Wm2, Wp1c
    __shared__ float sB[3 * 32];     // bm1, bm2, bp1
    __shared__ float sWp2[32];
    __shared__ float sbp2;

    int tid = threadIdx.x;
    for (int i = tid; i < 1024; i += 256) {
        sW[i]        = Wm1[i];
        sW[1024 + i] = Wm2[i];
        sW[2048 + i] = Wp1[512 * 32 + i];   // rows 512..543
    }
    if (tid < 32) {
        sB[tid]      = bm1[tid];
        sB[32 + tid] = bm2[tid];
        sB[64 + tid] = bp1[tid];
        sWp2[tid]    = Wp2[tid];
    }
    if (tid == 0) sbp2 = bp2[0];
    __syncthreads();

    int e = blockIdx.x * blockDim.x + tid;
    if (e >= NE) return;

    int r = EI[e], c = EI[NE + e];

    float in[32];
    {
        const float4* ep = (const float4*)(EA + (size_t)e * 32);
        #pragma unroll
        for (int q = 0; q < 8; q++) {
            float4 v = ep[q];
            in[q * 4 + 0] = v.x; in[q * 4 + 1] = v.y;
            in[q * 4 + 2] = v.z; in[q * 4 + 3] = v.w;
        }
    }

    const float4* pa = (const float4*)(g_P + (size_t)r * 64);
    const float4* pb = (const float4*)(g_P + (size_t)c * 64 + 32);

    #pragma unroll 1
    for (int L = 0; L < 3; L++) {
        const float4* w4 = (const float4*)(sW + L * 1024);
        const float4* b4 = (const float4*)(sB + L * 32);
        float4 acc[8];
        #pragma unroll
        for (int j = 0; j < 8; j++) acc[j] = b4[j];
        if (L == 2) {
            #pragma unroll
            for (int j = 0; j < 8; j++) {
                float4 x = pa[j], y = pb[j];
                acc[j].x += x.x + y.x; acc[j].y += x.y + y.y;
                acc[j].z += x.z + y.z; acc[j].w += x.w + y.w;
            }
        }
        #pragma unroll
        for (int k = 0; k < 32; k++) {
            float v = in[k];
            #pragma unroll
            for (int j = 0; j < 8; j++) {
                float4 w = w4[k * 8 + j];
                acc[j].x = fmaf(v, w.x, acc[j].x);
                acc[j].y = fmaf(v, w.y, acc[j].y);
                acc[j].z = fmaf(v, w.z, acc[j].z);
                acc[j].w = fmaf(v, w.w, acc[j].w);
            }
        }
        #pragma unroll
        for (int j = 0; j < 8; j++) {
            in[j * 4 + 0] = fmaxf(acc[j].x, 0.f);
            in[j * 4 + 1] = fmaxf(acc[j].y, 0.f);
            in[j * 4 + 2] = fmaxf(acc[j].z, 0.f);
            in[j * 4 + 3] = fmaxf(acc[j].w, 0.f);
        }
    }

    float s = sbp2;
    #pragma unroll
    for (int j = 0; j < 32; j++) s = fmaf(in[j], sWp2[j], s);
    OUT[e] = s;
}

// ---------------- launch ----------------
extern "C" void kernel_launch(void* const* d_in, const int* in_sizes, int n_in,
                              void* d_out, int out_size) {
    const float* x    = (const float*)d_in[0];
    const int*   ei   = (const int*)d_in[1];
    const float* ea   = (const float*)d_in[2];
    const float* W1   = (const float*)d_in[3];
    const float* as1  = (const float*)d_in[4];
    const float* ad1  = (const float*)d_in[5];
    const float* b1   = (const float*)d_in[6];
    const float* W2   = (const float*)d_in[7];
    const float* as2  = (const float*)d_in[8];
    const float* ad2  = (const float*)d_in[9];
    const float* b2   = (const float*)d_in[10];
    const float* Wm1  = (const float*)d_in[11];
    const float* bm1  = (const float*)d_in[12];
    const float* Wm2  = (const float*)d_in[13];
    const float* bm2  = (const float*)d_in[14];
    const float* Wp1  = (const float*)d_in[15];
    const float* bp1  = (const float*)d_in[16];
    const float* Wp2  = (const float*)d_in[17];
    const float* bp2  = (const float*)d_in[18];
    float* out = (float*)d_out;

    float *ph, *px, *pP, *pWpab;
    cudaGetSymbolAddress((void**)&ph,    g_h);
    cudaGetSymbolAddress((void**)&px,    g_x);
    cudaGetSymbolAddress((void**)&pP,    g_P);
    cudaGetSymbolAddress((void**)&pWpab, g_Wpab);

    // CSR
    {
        int* degp; cudaGetSymbolAddress((void**)&degp, g_deg);
        k_zero<<<(NN + 255) / 256, 256>>>(degp, NN);
    }
    k_count<<<(NE + 255) / 256, 256>>>(ei);
    k_scan<<<1, 1024>>>();
    k_fill<<<(NE + 255) / 256, 256>>>(ei);
    k_packWp1<<<(256 * 64 + 255) / 256, 256>>>(Wp1);

    dim3 g1(F / 128, (NN + 127) / 128);
    int nwBlocks = (NN * 32 + 255) / 256;

    // layer 1
    k_gemm128<<<g1, 256>>>(x, W1, ph, NN, F, NODE_IN);
    k_attn<<<nwBlocks, 256>>>(ph, as1, ad1);
    k_agg<<<nwBlocks, 256>>>(ph, b1, px);

    // layer 2
    k_gemm128<<<g1, 256>>>(px, W2, ph, NN, F, F);
    k_attn<<<nwBlocks, 256>>>(ph, as2, ad2);
    k_agg<<<nwBlocks, 256>>>(ph, b2, px);

    // node-side predictor partials: P = x @ [Wp1_a | Wp1_b]  (N=64)
    dim3 gp(1, (NN + 127) / 128);
    k_gemm<<<gp, 256>>>(px, pWpab, pP, NN, 64, 256);

    // edge predictor
    k_pred<<<(NE + 255) / 256, 256>>>(ei, ea, Wm1, bm1, Wm2, bm2,
                                      Wp1, bp1, Wp2, bp2, out);
}

// round 7
// speedup vs baseline: 2.5248x; 1.2966x over previous
#include <cuda_runtime.h>
#include <cuda_bf16.h>
#include <cstdint>

#define FULL 0xffffffffu

static constexpr int NN      = 50000;
static constexpr int NE      = 400000;
static constexpr int NODE_IN = 128;
static constexpr int F       = 256;   // HEADS*HID
static constexpr int HEADS   = 8;
static constexpr float SLOPE = 0.2f;
static constexpr int MPAD    = 50048; // 391 * 128

// ---------------- scratch (device globals; no allocation allowed) ----------------
__device__ float g_h[(size_t)NN * F];   // pre-aggregation node features
__device__ float g_x[(size_t)NN * F];   // post-layer node features
__device__ float g_P[(size_t)NN * 64];  // per-node predictor partials [Pa|Pb]
__device__ __nv_bfloat16 g_Ah[(size_t)MPAD * 256];
__device__ __nv_bfloat16 g_Al[(size_t)MPAD * 256];
__device__ __nv_bfloat16 g_Bh[256 * 256];
__device__ __nv_bfloat16 g_Bl[256 * 256];
__device__ float g_as[NN * HEADS];
__device__ float g_ad[NN * HEADS];
__device__ int   g_deg[NN];
__device__ int   g_off[NN + 1];
__device__ int   g_cur[NN];
__device__ int   g_col[NE];

__device__ __forceinline__ float lrelu(float x) { return x > 0.f ? x : SLOPE * x; }

__device__ __forceinline__ uint32_t smem_u32(const void* p) {
    uint32_t a;
    asm("{ .reg .u64 t; cvta.to.shared.u64 t, %1; cvt.u32.u64 %0, t; }" : "=r"(a) : "l"(p));
    return a;
}
__device__ __forceinline__ void ldsm4(uint32_t* r, uint32_t addr) {
    asm volatile("ldmatrix.sync.aligned.m8n8.x4.shared.b16 {%0,%1,%2,%3}, [%4];"
                 : "=r"(r[0]), "=r"(r[1]), "=r"(r[2]), "=r"(r[3]) : "r"(addr));
}
__device__ __forceinline__ void mma16816(float* c, const uint32_t* a, const uint32_t* b) {
    asm volatile("mma.sync.aligned.m16n8k16.row.col.f32.bf16.bf16.f32 "
                 "{%0,%1,%2,%3}, {%4,%5,%6,%7}, {%8,%9}, {%0,%1,%2,%3};"
                 : "+f"(c[0]), "+f"(c[1]), "+f"(c[2]), "+f"(c[3])
                 : "r"(a[0]), "r"(a[1]), "r"(a[2]), "r"(a[3]), "r"(b[0]), "r"(b[1]));
}

// ---------------- CSR build ----------------
__global__ void k_zero(int* p, int n) {
    int i = blockIdx.x * blockDim.x + threadIdx.x;
    if (i < n) p[i] = 0;
}
__global__ void k_count(const int* __restrict__ ei) {
    int e = blockIdx.x * blockDim.x + threadIdx.x;
    if (e < NE) atomicAdd(&g_deg[ei[NE + e]], 1);
}
__global__ void k_scan() {
    __shared__ int sh[32];
    __shared__ int s_carry;
    int tid = threadIdx.x;
    if (tid == 0) s_carry = 0;
    __syncthreads();
    for (int base = 0; base < NN; base += 1024) {
        int v = (base + tid < NN) ? g_deg[base + tid] : 0;
        int x = v;
        #pragma unroll
        for (int d = 1; d < 32; d <<= 1) {
            int y = __shfl_up_sync(FULL, x, d);
            if ((tid & 31) >= d) x += y;
        }
        if ((tid & 31) == 31) sh[tid >> 5] = x;
        __syncthreads();
        if (tid < 32) {
            int w = sh[tid];
            int wx = w;
            #pragma unroll
            for (int d = 1; d < 32; d <<= 1) {
                int y = __shfl_up_sync(FULL, wx, d);
                if (tid >= d) wx += y;
            }
            sh[tid] = wx - w;
        }
        __syncthreads();
        int incl = x + sh[tid >> 5];
        int excl = incl - v;
        int carry = s_carry;
        if (base + tid < NN) {
            g_off[base + tid] = carry + excl;
            g_cur[base + tid] = carry + excl;
        }
        __syncthreads();
        if (tid == 1023) s_carry = carry + incl;
        __syncthreads();
    }
    if (tid == 0) g_off[NN] = s_carry;
}
__global__ void k_fill(const int* __restrict__ ei) {
    int e = blockIdx.x * blockDim.x + threadIdx.x;
    if (e < NE) {
        int s = ei[e], d = ei[NE + e];
        int p = atomicAdd(&g_cur[d], 1);
        g_col[p] = s;
    }
}

// ---------------- precision-split conversions ----------------
__global__ void k_splitA(const float* __restrict__ A, int total4) {
    int i = blockIdx.x * blockDim.x + threadIdx.x;
    if (i >= total4) return;
    float4 v = ((const float4*)A)[i];
    ushort4 h, l;
    float f;
    __nv_bfloat16 b;
    b = __float2bfloat16_rn(v.x); f = v.x - __bfloat162float(b); h.x = __bfloat16_as_ushort(b); l.x = __bfloat16_as_ushort(__float2bfloat16_rn(f));
    b = __float2bfloat16_rn(v.y); f = v.y - __bfloat162float(b); h.y = __bfloat16_as_ushort(b); l.y = __bfloat16_as_ushort(__float2bfloat16_rn(f));
    b = __float2bfloat16_rn(v.z); f = v.z - __bfloat162float(b); h.z = __bfloat16_as_ushort(b); l.z = __bfloat16_as_ushort(__float2bfloat16_rn(f));
    b = __float2bfloat16_rn(v.w); f = v.w - __bfloat162float(b); h.w = __bfloat16_as_ushort(b); l.w = __bfloat16_as_ushort(__float2bfloat16_rn(f));
    ((ushort4*)g_Ah)[i] = h;
    ((ushort4*)g_Al)[i] = l;
}

// W [K,N] fp32 -> B operand [N][K] bf16 hi/lo (K-major, i.e. "col" for mma)
__global__ void k_splitW(const float* __restrict__ W, int K, int N) {
    int i = blockIdx.x * blockDim.x + threadIdx.x;
    if (i >= N * K) return;
    int n = i / K, k = i % K;
    float v = W[(size_t)k * N + n];
    __nv_bfloat16 hi = __float2bfloat16_rn(v);
    g_Bh[i] = hi;
    g_Bl[i] = __float2bfloat16_rn(v - __bfloat162float(hi));
}

// Wp1 [544,32] -> B operand [128 pad][256]: n 0..31 = Wp1_a, 32..63 = Wp1_b, 64..127 = 0
__global__ void k_splitWp(const float* __restrict__ Wp1) {
    int i = blockIdx.x * blockDim.x + threadIdx.x;
    if (i >= 128 * 256) return;
    int n = i / 256, k = i % 256;
    float v = 0.f;
    if (n < 32)      v = Wp1[(size_t)k * 32 + n];
    else if (n < 64) v = Wp1[(size_t)(256 + k) * 32 + (n - 32)];
    __nv_bfloat16 hi = __float2bfloat16_rn(v);
    g_Bh[i] = hi;
    g_Bl[i] = __float2bfloat16_rn(v - __bfloat162float(hi));
}

// ---------------- mma.sync split-bf16 GEMM: C[m,n] = sum_k A[m,k] * B[n,k] ----------------
// CTA tile 128x128, BK=32; 8 warps (2 x 4), warp tile 64x32.
static constexpr int PADK = 40;   // row stride in bf16 elems (conflict-free ldmatrix)

__global__ __launch_bounds__(256) void k_mma(const __nv_bfloat16* __restrict__ Ah,
                                             const __nv_bfloat16* __restrict__ Al,
                                             const __nv_bfloat16* __restrict__ Bh,
                                             const __nv_bfloat16* __restrict__ Bl,
                                             float* __restrict__ C,
                                             int M, int Nstore, int K, int ldc) {
    __shared__ __align__(16) uint16_t sAh[128 * PADK];
    __shared__ __align__(16) uint16_t sAl[128 * PADK];
    __shared__ __align__(16) uint16_t sBh[128 * PADK];
    __shared__ __align__(16) uint16_t sBl[128 * PADK];

    int tid = threadIdx.x, lane = tid & 31, wid = tid >> 5;
    int wm = wid & 1, wn = wid >> 1;              // warp tile origin: (wm*64, wn*32)
    int bm = blockIdx.y * 128, bn = blockIdx.x * 128;

    float acc[4][4][4];
    #pragma unroll
    for (int mi = 0; mi < 4; mi++)
        #pragma unroll
        for (int ni = 0; ni < 4; ni++)
            #pragma unroll
            for (int j = 0; j < 4; j++) acc[mi][ni][j] = 0.f;

    for (int k0 = 0; k0 < K; k0 += 32) {
        __syncthreads();
        #pragma unroll
        for (int t = 0; t < 2; t++) {
            int u = tid + t * 256;
            int r = u >> 2, c8 = (u & 3) * 8;
            size_t ga = (size_t)(bm + r) * K + k0 + c8;
            size_t gb = (size_t)(bn + r) * K + k0 + c8;
            *(uint4*)&sAh[r * PADK + c8] = *(const uint4*)(Ah + ga);
            *(uint4*)&sAl[r * PADK + c8] = *(const uint4*)(Al + ga);
            *(uint4*)&sBh[r * PADK + c8] = *(const uint4*)(Bh + gb);
            *(uint4*)&sBl[r * PADK + c8] = *(const uint4*)(Bl + gb);
        }
        __syncthreads();

        #pragma unroll
        for (int ks = 0; ks < 2; ks++) {
            int kb = ks * 16;
            uint32_t ah[4][4], al[4][4], bh[4][2], bl[4][2];
            // A fragments: x4 tiles = (m0-7,k0-7)(m8-15,k0-7)(m0-7,k8-15)(m8-15,k8-15)
            #pragma unroll
            for (int mi = 0; mi < 4; mi++) {
                int row = wm * 64 + mi * 16 + (lane & 15);
                int kc  = kb + (lane >> 4) * 8;
                ldsm4(ah[mi], smem_u32(&sAh[row * PADK + kc]));
                ldsm4(al[mi], smem_u32(&sAl[row * PADK + kc]));
            }
            // B fragments: one x4 covers two n-octets (b0,b1 for each)
            #pragma unroll
            for (int g = 0; g < 2; g++) {
                int tI = lane >> 3;
                int nrow = wn * 32 + g * 16 + (tI >> 1) * 8 + (lane & 7);
                int kc   = kb + (tI & 1) * 8;
                uint32_t r4[4];
                ldsm4(r4, smem_u32(&sBh[nrow * PADK + kc]));
                bh[g * 2][0] = r4[0]; bh[g * 2][1] = r4[1];
                bh[g * 2 + 1][0] = r4[2]; bh[g * 2 + 1][1] = r4[3];
                ldsm4(r4, smem_u32(&sBl[nrow * PADK + kc]));
                bl[g * 2][0] = r4[0]; bl[g * 2][1] = r4[1];
                bl[g * 2 + 1][0] = r4[2]; bl[g * 2 + 1][1] = r4[3];
            }
            #pragma unroll
            for (int mi = 0; mi < 4; mi++)
                #pragma unroll
                for (int ni = 0; ni < 4; ni++) {
                    mma16816(acc[mi][ni], ah[mi], bh[ni]);
                    mma16816(acc[mi][ni], ah[mi], bl[ni]);
                    mma16816(acc[mi][ni], al[mi], bh[ni]);
                }
        }
    }

    // epilogue: c0,c1 -> (m = t/4, n = 2(t%4)); c2,c3 -> m+8
    #pragma unroll
    for (int mi = 0; mi < 4; mi++) {
        int m0 = bm + wm * 64 + mi * 16 + (lane >> 2);
        #pragma unroll
        for (int ni = 0; ni < 4; ni++) {
            int c0 = bn + wn * 32 + ni * 8 + (lane & 3) * 2;
            if (c0 < Nstore) {
                if (m0 < M)
                    *(float2*)&C[(size_t)m0 * ldc + c0] =
                        make_float2(acc[mi][ni][0], acc[mi][ni][1]);
                if (m0 + 8 < M)
                    *(float2*)&C[(size_t)(m0 + 8) * ldc + c0] =
                        make_float2(acc[mi][ni][2], acc[mi][ni][3]);
            }
        }
    }
}

// ---------------- attention coefficients ----------------
__global__ void k_attn(const float* __restrict__ h, const float* __restrict__ a_src,
                       const float* __restrict__ a_dst) {
    int warp = (blockIdx.x * blockDim.x + threadIdx.x) >> 5;
    int lane = threadIdx.x & 31;
    if (warp >= NN) return;
    int head = lane >> 2, part = lane & 3;
    const float4* hp = (const float4*)(h + (size_t)warp * F + head * 32 + part * 8);
    const float4* ap = (const float4*)(a_src + head * 32 + part * 8);
    const float4* dp = (const float4*)(a_dst + head * 32 + part * 8);
    float4 h0 = hp[0], h1 = hp[1];
    float4 a0 = ap[0], a1 = ap[1];
    float4 d0 = dp[0], d1 = dp[1];
    float s = h0.x * a0.x + h0.y * a0.y + h0.z * a0.z + h0.w * a0.w
            + h1.x * a1.x + h1.y * a1.y + h1.z * a1.z + h1.w * a1.w;
    float d = h0.x * d0.x + h0.y * d0.y + h0.z * d0.z + h0.w * d0.w
            + h1.x * d1.x + h1.y * d1.y + h1.z * d1.z + h1.w * d1.w;
    s += __shfl_xor_sync(FULL, s, 1); s += __shfl_xor_sync(FULL, s, 2);
    d += __shfl_xor_sync(FULL, d, 1); d += __shfl_xor_sync(FULL, d, 2);
    if (part == 0) {
        g_as[warp * HEADS + head] = s;
        g_ad[warp * HEADS + head] = d;
    }
}

// ---------------- GAT segment-softmax aggregation (warp per node) ----------------
__global__ void k_agg(const float* __restrict__ h, const float* __restrict__ bias,
                      float* __restrict__ out) {
    int n = (blockIdx.x * blockDim.x + threadIdx.x) >> 5;
    int lane = threadIdx.x & 31;
    if (n >= NN) return;
    int head = lane >> 2, part = lane & 3;

    float adv = g_ad[n * HEADS + head];
    float e_self = lrelu(g_as[n * HEADS + head] + adv);
    int beg = g_off[n], end = g_off[n + 1];

    float m = e_self;
    for (int i = beg; i < end; i++) {
        int s = g_col[i];
        m = fmaxf(m, lrelu(g_as[s * HEADS + head] + adv));
    }

    float w = __expf(e_self - m);
    float denom = w;
    const float4* hp = (const float4*)(h + (size_t)n * F + head * 32 + part * 8);
    float4 v0 = hp[0], v1 = hp[1];
    float4 acc0 = make_float4(w * v0.x, w * v0.y, w * v0.z, w * v0.w);
    float4 acc1 = make_float4(w * v1.x, w * v1.y, w * v1.z, w * v1.w);
    for (int i = beg; i < end; i++) {
        int s = g_col[i];
        float ww = __expf(lrelu(g_as[s * HEADS + head] + adv) - m);
        denom += ww;
        const float4* sp = (const float4*)(h + (size_t)s * F + head * 32 + part * 8);
        float4 s0 = sp[0], s1 = sp[1];
        acc0.x = fmaf(ww, s0.x, acc0.x); acc0.y = fmaf(ww, s0.y, acc0.y);
        acc0.z = fmaf(ww, s0.z, acc0.z); acc0.w = fmaf(ww, s0.w, acc0.w);
        acc1.x = fmaf(ww, s1.x, acc1.x); acc1.y = fmaf(ww, s1.y, acc1.y);
        acc1.z = fmaf(ww, s1.z, acc1.z); acc1.w = fmaf(ww, s1.w, acc1.w);
    }
    float inv = 1.f / denom;
    const float4* bp = (const float4*)(bias + head * 32 + part * 8);
    float4 b0 = bp[0], b1 = bp[1];
    float4 o0, o1;
    o0.x = fmaxf(fmaf(acc0.x, inv, b0.x), 0.f);
    o0.y = fmaxf(fmaf(acc0.y, inv, b0.y), 0.f);
    o0.z = fmaxf(fmaf(acc0.z, inv, b0.z), 0.f);
    o0.w = fmaxf(fmaf(acc0.w, inv, b0.w), 0.f);
    o1.x = fmaxf(fmaf(acc1.x, inv, b1.x), 0.f);
    o1.y = fmaxf(fmaf(acc1.y, inv, b1.y), 0.f);
    o1.z = fmaxf(fmaf(acc1.z, inv, b1.z), 0.f);
    o1.w = fmaxf(fmaf(acc1.w, inv, b1.w), 0.f);
    float4* op = (float4*)(out + (size_t)n * F + head * 32 + part * 8);
    op[0] = o0; op[1] = o1;
}

// ---------------- edge predictor: thread per edge ----------------
__global__ __launch_bounds__(256) void k_pred(const int* __restrict__ EI,
                                              const float* __restrict__ EA,
                                              const float* __restrict__ Wm1,
                                              const float* __restrict__ bm1,
                                              const float* __restrict__ Wm2,
                                              const float* __restrict__ bm2,
                                              const float* __restrict__ Wp1,
                                              const float* __restrict__ bp1,
                                              const float* __restrict__ Wp2,
                                              const float* __restrict__ bp2,
                                              float* __restrict__ OUT) {
    __shared__ float sW[3 * 1024];
    __shared__ float sB[3 * 32];
    __shared__ float sWp2[32];
    __shared__ float sbp2;

    int tid = threadIdx.x;
    for (int i = tid; i < 1024; i += 256) {
        sW[i]        = Wm1[i];
        sW[1024 + i] = Wm2[i];
        sW[2048 + i] = Wp1[512 * 32 + i];
    }
    if (tid < 32) {
        sB[tid]      = bm1[tid];
        sB[32 + tid] = bm2[tid];
        sB[64 + tid] = bp1[tid];
        sWp2[tid]    = Wp2[tid];
    }
    if (tid == 0) sbp2 = bp2[0];
    __syncthreads();

    int e = blockIdx.x * blockDim.x + tid;
    if (e >= NE) return;

    int r = EI[e], c = EI[NE + e];

    float in[32];
    {
        const float4* ep = (const float4*)(EA + (size_t)e * 32);
        #pragma unroll
        for (int q = 0; q < 8; q++) {
            float4 v = ep[q];
            in[q * 4 + 0] = v.x; in[q * 4 + 1] = v.y;
            in[q * 4 + 2] = v.z; in[q * 4 + 3] = v.w;
        }
    }

    const float4* pa = (const float4*)(g_P + (size_t)r * 64);
    const float4* pb = (const float4*)(g_P + (size_t)c * 64 + 32);

    #pragma unroll 1
    for (int L = 0; L < 3; L++) {
        const float4* w4 = (const float4*)(sW + L * 1024);
        const float4* b4 = (const float4*)(sB + L * 32);
        float4 acc[8];
        #pragma unroll
        for (int j = 0; j < 8; j++) acc[j] = b4[j];
        if (L == 2) {
            #pragma unroll
            for (int j = 0; j < 8; j++) {
                float4 x = pa[j], y = pb[j];
                acc[j].x += x.x + y.x; acc[j].y += x.y + y.y;
                acc[j].z += x.z + y.z; acc[j].w += x.w + y.w;
            }
        }
        #pragma unroll
        for (int k = 0; k < 32; k++) {
            float v = in[k];
            #pragma unroll
            for (int j = 0; j < 8; j++) {
                float4 w = w4[k * 8 + j];
                acc[j].x = fmaf(v, w.x, acc[j].x);
                acc[j].y = fmaf(v, w.y, acc[j].y);
                acc[j].z = fmaf(v, w.z, acc[j].z);
                acc[j].w = fmaf(v, w.w, acc[j].w);
            }
        }
        #pragma unroll
        for (int j = 0; j < 8; j++) {
            in[j * 4 + 0] = fmaxf(acc[j].x, 0.f);
            in[j * 4 + 1] = fmaxf(acc[j].y, 0.f);
            in[j * 4 + 2] = fmaxf(acc[j].z, 0.f);
            in[j * 4 + 3] = fmaxf(acc[j].w, 0.f);
        }
    }

    float s = sbp2;
    #pragma unroll
    for (int j = 0; j < 32; j++) s = fmaf(in[j], sWp2[j], s);
    OUT[e] = s;
}

// ---------------- launch ----------------
extern "C" void kernel_launch(void* const* d_in, const int* in_sizes, int n_in,
                              void* d_out, int out_size) {
    const float* x    = (const float*)d_in[0];
    const int*   ei   = (const int*)d_in[1];
    const float* ea   = (const float*)d_in[2];
    const float* W1   = (const float*)d_in[3];
    const float* as1  = (const float*)d_in[4];
    const float* ad1  = (const float*)d_in[5];
    const float* b1   = (const float*)d_in[6];
    const float* W2   = (const float*)d_in[7];
    const float* as2  = (const float*)d_in[8];
    const float* ad2  = (const float*)d_in[9];
    const float* b2   = (const float*)d_in[10];
    const float* Wm1  = (const float*)d_in[11];
    const float* bm1  = (const float*)d_in[12];
    const float* Wm2  = (const float*)d_in[13];
    const float* bm2  = (const float*)d_in[14];
    const float* Wp1  = (const float*)d_in[15];
    const float* bp1  = (const float*)d_in[16];
    const float* Wp2  = (const float*)d_in[17];
    const float* bp2  = (const float*)d_in[18];
    float* out = (float*)d_out;

    float *ph, *px, *pP;
    __nv_bfloat16 *pAh, *pAl, *pBh, *pBl;
    cudaGetSymbolAddress((void**)&ph,  g_h);
    cudaGetSymbolAddress((void**)&px,  g_x);
    cudaGetSymbolAddress((void**)&pP,  g_P);
    cudaGetSymbolAddress((void**)&pAh, g_Ah);
    cudaGetSymbolAddress((void**)&pAl, g_Al);
    cudaGetSymbolAddress((void**)&pBh, g_Bh);
    cudaGetSymbolAddress((void**)&pBl, g_Bl);

    // CSR
    {
        int* degp; cudaGetSymbolAddress((void**)&degp, g_deg);
        k_zero<<<(NN + 255) / 256, 256>>>(degp, NN);
    }
    k_count<<<(NE + 255) / 256, 256>>>(ei);
    k_scan<<<1, 1024>>>();
    k_fill<<<(NE + 255) / 256, 256>>>(ei);

    int nwBlocks = (NN * 32 + 255) / 256;
    int tilesM = MPAD / 128;   // 391

    // ---- layer 1:  h = x @ W1 ----
    k_splitW<<<(256 * NODE_IN + 255) / 256, 256>>>(W1, NODE_IN, F);
    {
        int t4 = NN * NODE_IN / 4;
        k_splitA<<<(t4 + 255) / 256, 256>>>(x, t4);
    }
    k_mma<<<dim3(2, tilesM), 256>>>(pAh, pAl, pBh, pBl, ph, NN, F, NODE_IN, F);
    k_attn<<<nwBlocks, 256>>>(ph, as1, ad1);
    k_agg<<<nwBlocks, 256>>>(ph, b1, px);

    // ---- layer 2:  h = x @ W2 ----
    k_splitW<<<(256 * 256 + 255) / 256, 256>>>(W2, F, F);
    {
        int t4 = NN * F / 4;
        k_splitA<<<(t4 + 255) / 256, 256>>>(px, t4);
    }
    k_mma<<<dim3(2, tilesM), 256>>>(pAh, pAl, pBh, pBl, ph, NN, F, F, F);
    k_attn<<<nwBlocks, 256>>>(ph, as2, ad2);
    k_agg<<<nwBlocks, 256>>>(ph, b2, px);

    // ---- node-side predictor partials: P = x @ [Wp1_a | Wp1_b] ----
    k_splitWp<<<(128 * 256 + 255) / 256, 256>>>(Wp1);
    {
        int t4 = NN * F / 4;
        k_splitA<<<(t4 + 255) / 256, 256>>>(px, t4);
    }
    k_mma<<<dim3(1, tilesM), 256>>>(pAh, pAl, pBh, pBl, pP, NN, 64, F, 64);

    // ---- edge predictor ----
    k_pred<<<(NE + 255) / 256, 256>>>(ei, ea, Wm1, bm1, Wm2, bm2,
                                      Wp1, bp1, Wp2, bp2, out);
}

// round 9
// speedup vs baseline: 2.7463x; 1.0877x over previous
#include <cuda_runtime.h>
#include <cuda_bf16.h>
#include <cstdint>

#define FULL 0xffffffffu

static constexpr int NN      = 50000;
static constexpr int NE      = 400000;
static constexpr int NODE_IN = 128;
static constexpr int F       = 256;   // HEADS*HID
static constexpr int HEADS   = 8;
static constexpr float SLOPE = 0.2f;
static constexpr int MPAD    = 50048; // 391 * 128

// ---------------- scratch (device globals; no allocation allowed) ----------------
__device__ float g_h[(size_t)NN * F];   // pre-aggregation node features
__device__ float g_P[(size_t)NN * 64];  // per-node predictor partials [Pa|Pb]
__device__ __nv_bfloat16 g_Ah[(size_t)MPAD * 256];
__device__ __nv_bfloat16 g_Al[(size_t)MPAD * 256];
__device__ __nv_bfloat16 g_Bh[256 * 256];
__device__ __nv_bfloat16 g_Bl[256 * 256];
__device__ float g_as[NN * HEADS];
__device__ float g_ad[NN * HEADS];
__device__ int   g_deg[NN];
__device__ int   g_off[NN + 1];
__device__ int   g_cur[NN];
__device__ int   g_col[NE];

__device__ __forceinline__ float lrelu(float x) { return x > 0.f ? x : SLOPE * x; }

__device__ __forceinline__ uint32_t smem_u32(const void* p) {
    uint32_t a;
    asm("{ .reg .u64 t; cvta.to.shared.u64 t, %1; cvt.u32.u64 %0, t; }" : "=r"(a) : "l"(p));
    return a;
}
__device__ __forceinline__ void ldsm4(uint32_t* r, uint32_t addr) {
    asm volatile("ldmatrix.sync.aligned.m8n8.x4.shared.b16 {%0,%1,%2,%3}, [%4];"
                 : "=r"(r[0]), "=r"(r[1]), "=r"(r[2]), "=r"(r[3]) : "r"(addr));
}
__device__ __forceinline__ void mma16816(float* c, const uint32_t* a, const uint32_t* b) {
    asm volatile("mma.sync.aligned.m16n8k16.row.col.f32.bf16.bf16.f32 "
                 "{%0,%1,%2,%3}, {%4,%5,%6,%7}, {%8,%9}, {%0,%1,%2,%3};"
                 : "+f"(c[0]), "+f"(c[1]), "+f"(c[2]), "+f"(c[3])
                 : "r"(a[0]), "r"(a[1]), "r"(a[2]), "r"(a[3]), "r"(b[0]), "r"(b[1]));
}

// ---------------- CSR build ----------------
__global__ void k_zero(int* p, int n) {
    int i = blockIdx.x * blockDim.x + threadIdx.x;
    if (i < n) p[i] = 0;
}
__global__ void k_count(const int* __restrict__ ei) {
    int e = blockIdx.x * blockDim.x + threadIdx.x;
    if (e < NE) atomicAdd(&g_deg[ei[NE + e]], 1);
}
__global__ void k_scan() {
    __shared__ int sh[32];
    __shared__ int s_carry;
    int tid = threadIdx.x;
    if (tid == 0) s_carry = 0;
    __syncthreads();
    for (int base = 0; base < NN; base += 1024) {
        int v = (base + tid < NN) ? g_deg[base + tid] : 0;
        int x = v;
        #pragma unroll
        for (int d = 1; d < 32; d <<= 1) {
            int y = __shfl_up_sync(FULL, x, d);
            if ((tid & 31) >= d) x += y;
        }
        if ((tid & 31) == 31) sh[tid >> 5] = x;
        __syncthreads();
        if (tid < 32) {
            int w = sh[tid];
            int wx = w;
            #pragma unroll
            for (int d = 1; d < 32; d <<= 1) {
                int y = __shfl_up_sync(FULL, wx, d);
                if (tid >= d) wx += y;
            }
            sh[tid] = wx - w;
        }
        __syncthreads();
        int incl = x + sh[tid >> 5];
        int excl = incl - v;
        int carry = s_carry;
        if (base + tid < NN) {
            g_off[base + tid] = carry + excl;
            g_cur[base + tid] = carry + excl;
        }
        __syncthreads();
        if (tid == 1023) s_carry = carry + incl;
        __syncthreads();
    }
    if (tid == 0) g_off[NN] = s_carry;
}
__global__ void k_fill(const int* __restrict__ ei) {
    int e = blockIdx.x * blockDim.x + threadIdx.x;
    if (e < NE) {
        int s = ei[e], d = ei[NE + e];
        int p = atomicAdd(&g_cur[d], 1);
        g_col[p] = s;
    }
}

// ---------------- precision-split conversions ----------------
__global__ void k_splitA(const float* __restrict__ A, int total4) {
    int i = blockIdx.x * blockDim.x + threadIdx.x;
    if (i >= total4) return;
    float4 v = ((const float4*)A)[i];
    ushort4 h, l;
    float f;
    __nv_bfloat16 b;
    b = __float2bfloat16_rn(v.x); f = v.x - __bfloat162float(b); h.x = __bfloat16_as_ushort(b); l.x = __bfloat16_as_ushort(__float2bfloat16_rn(f));
    b = __float2bfloat16_rn(v.y); f = v.y - __bfloat162float(b); h.y = __bfloat16_as_ushort(b); l.y = __bfloat16_as_ushort(__float2bfloat16_rn(f));
    b = __float2bfloat16_rn(v.z); f = v.z - __bfloat162float(b); h.z = __bfloat16_as_ushort(b); l.z = __bfloat16_as_ushort(__float2bfloat16_rn(f));
    b = __float2bfloat16_rn(v.w); f = v.w - __bfloat162float(b); h.w = __bfloat16_as_ushort(b); l.w = __bfloat16_as_ushort(__float2bfloat16_rn(f));
    ((ushort4*)g_Ah)[i] = h;
    ((ushort4*)g_Al)[i] = l;
}

// W [K,N] fp32 -> B operand [N][K] bf16 hi/lo (K-major, i.e. "col" for mma)
__global__ void k_splitW(const float* __restrict__ W, int K, int N) {
    int i = blockIdx.x * blockDim.x + threadIdx.x;
    if (i >= N * K) return;
    int n = i / K, k = i % K;
    float v = W[(size_t)k * N + n];
    __nv_bfloat16 hi = __float2bfloat16_rn(v);
    g_Bh[i] = hi;
    g_Bl[i] = __float2bfloat16_rn(v - __bfloat162float(hi));
}

// Wp1 [544,32] -> B operand [128 pad][256]: n 0..31 = Wp1_a, 32..63 = Wp1_b, 64..127 = 0
__global__ void k_splitWp(const float* __restrict__ Wp1) {
    int i = blockIdx.x * blockDim.x + threadIdx.x;
    if (i >= 128 * 256) return;
    int n = i / 256, k = i % 256;
    float v = 0.f;
    if (n < 32)      v = Wp1[(size_t)k * 32 + n];
    else if (n < 64) v = Wp1[(size_t)(256 + k) * 32 + (n - 32)];
    __nv_bfloat16 hi = __float2bfloat16_rn(v);
    g_Bh[i] = hi;
    g_Bl[i] = __float2bfloat16_rn(v - __bfloat162float(hi));
}

// ---------------- mma.sync split-bf16 GEMM: C[m,n] = sum_k A[m,k] * B[n,k] ----------------
// CTA tile 128x128, BK=32; 8 warps (2 x 4), warp tile 64x32.
static constexpr int PADK = 40;   // row stride in bf16 elems (conflict-free ldmatrix)

__global__ __launch_bounds__(256) void k_mma(const __nv_bfloat16* __restrict__ Ah,
                                             const __nv_bfloat16* __restrict__ Al,
                                             const __nv_bfloat16* __restrict__ Bh,
                                             const __nv_bfloat16* __restrict__ Bl,
                                             float* __restrict__ C,
                                             int M, int Nstore, int K, int ldc) {
    __shared__ __align__(16) uint16_t sAh[128 * PADK];
    __shared__ __align__(16) uint16_t sAl[128 * PADK];
    __shared__ __align__(16) uint16_t sBh[128 * PADK];
    __shared__ __align__(16) uint16_t sBl[128 * PADK];

    int tid = threadIdx.x, lane = tid & 31, wid = tid >> 5;
    int wm = wid & 1, wn = wid >> 1;              // warp tile origin: (wm*64, wn*32)
    int bm = blockIdx.y * 128, bn = blockIdx.x * 128;

    float acc[4][4][4];
    #pragma unroll
    for (int mi = 0; mi < 4; mi++)
        #pragma unroll
        for (int ni = 0; ni < 4; ni++)
            #pragma unroll
            for (int j = 0; j < 4; j++) acc[mi][ni][j] = 0.f;

    for (int k0 = 0; k0 < K; k0 += 32) {
        __syncthreads();
        #pragma unroll
        for (int t = 0; t < 2; t++) {
            int u = tid + t * 256;
            int r = u >> 2, c8 = (u & 3) * 8;
            size_t ga = (size_t)(bm + r) * K + k0 + c8;
            size_t gb = (size_t)(bn + r) * K + k0 + c8;
            *(uint4*)&sAh[r * PADK + c8] = *(const uint4*)(Ah + ga);
            *(uint4*)&sAl[r * PADK + c8] = *(const uint4*)(Al + ga);
            *(uint4*)&sBh[r * PADK + c8] = *(const uint4*)(Bh + gb);
            *(uint4*)&sBl[r * PADK + c8] = *(const uint4*)(Bl + gb);
        }
        __syncthreads();

        #pragma unroll
        for (int ks = 0; ks < 2; ks++) {
            int kb = ks * 16;
            uint32_t ah[4][4], al[4][4], bh[4][2], bl[4][2];
            #pragma unroll
            for (int mi = 0; mi < 4; mi++) {
                int row = wm * 64 + mi * 16 + (lane & 15);
                int kc  = kb + (lane >> 4) * 8;
                ldsm4(ah[mi], smem_u32(&sAh[row * PADK + kc]));
                ldsm4(al[mi], smem_u32(&sAl[row * PADK + kc]));
            }
            #pragma unroll
            for (int g = 0; g < 2; g++) {
                int tI = lane >> 3;
                int nrow = wn * 32 + g * 16 + (tI >> 1) * 8 + (lane & 7);
                int kc   = kb + (tI & 1) * 8;
                uint32_t r4[4];
                ldsm4(r4, smem_u32(&sBh[nrow * PADK + kc]));
                bh[g * 2][0] = r4[0]; bh[g * 2][1] = r4[1];
                bh[g * 2 + 1][0] = r4[2]; bh[g * 2 + 1][1] = r4[3];
                ldsm4(r4, smem_u32(&sBl[nrow * PADK + kc]));
                bl[g * 2][0] = r4[0]; bl[g * 2][1] = r4[1];
                bl[g * 2 + 1][0] = r4[2]; bl[g * 2 + 1][1] = r4[3];
            }
            #pragma unroll
            for (int mi = 0; mi < 4; mi++)
                #pragma unroll
                for (int ni = 0; ni < 4; ni++) {
                    mma16816(acc[mi][ni], ah[mi], bh[ni]);
                    mma16816(acc[mi][ni], ah[mi], bl[ni]);
                    mma16816(acc[mi][ni], al[mi], bh[ni]);
                }
        }
    }

    #pragma unroll
    for (int mi = 0; mi < 4; mi++) {
        int m0 = bm + wm * 64 + mi * 16 + (lane >> 2);
        #pragma unroll
        for (int ni = 0; ni < 4; ni++) {
            int c0 = bn + wn * 32 + ni * 8 + (lane & 3) * 2;
            if (c0 < Nstore) {
                if (m0 < M)
                    *(float2*)&C[(size_t)m0 * ldc + c0] =
                        make_float2(acc[mi][ni][0], acc[mi][ni][1]);
                if (m0 + 8 < M)
                    *(float2*)&C[(size_t)(m0 + 8) * ldc + c0] =
                        make_float2(acc[mi][ni][2], acc[mi][ni][3]);
            }
        }
    }
}

// ---------------- attention coefficients ----------------
__global__ void k_attn(const float* __restrict__ h, const float* __restrict__ a_src,
                       const float* __restrict__ a_dst) {
    int warp = (blockIdx.x * blockDim.x + threadIdx.x) >> 5;
    int lane = threadIdx.x & 31;
    if (warp >= NN) return;
    int head = lane >> 2, part = lane & 3;
    const float4* hp = (const float4*)(h + (size_t)warp * F + head * 32 + part * 8);
    const float4* ap = (const float4*)(a_src + head * 32 + part * 8);
    const float4* dp = (const float4*)(a_dst + head * 32 + part * 8);
    float4 h0 = hp[0], h1 = hp[1];
    float4 a0 = ap[0], a1 = ap[1];
    float4 d0 = dp[0], d1 = dp[1];
    float s = h0.x * a0.x + h0.y * a0.y + h0.z * a0.z + h0.w * a0.w
            + h1.x * a1.x + h1.y * a1.y + h1.z * a1.z + h1.w * a1.w;
    float d = h0.x * d0.x + h0.y * d0.y + h0.z * d0.z + h0.w * d0.w
            + h1.x * d1.x + h1.y * d1.y + h1.z * d1.z + h1.w * d1.w;
    s += __shfl_xor_sync(FULL, s, 1); s += __shfl_xor_sync(FULL, s, 2);
    d += __shfl_xor_sync(FULL, d, 1); d += __shfl_xor_sync(FULL, d, 2);
    if (part == 0) {
        g_as[warp * HEADS + head] = s;
        g_ad[warp * HEADS + head] = d;
    }
}

// ---------------- GAT aggregation: online softmax, bf16 hi/lo epilogue ----------------
// warp per node; writes the relu'd output directly as split-bf16 A operand.
__global__ void k_agg(const float* __restrict__ h, const float* __restrict__ bias) {
    int n = (blockIdx.x * blockDim.x + threadIdx.x) >> 5;
    int lane = threadIdx.x & 31;
    if (n >= NN) return;
    int head = lane >> 2, part = lane & 3;

    float adv = g_ad[n * HEADS + head];
    float m = lrelu(g_as[n * HEADS + head] + adv);   // e_self
    float denom = 1.f;
    int beg = g_off[n], end = g_off[n + 1];

    const float4* hp = (const float4*)(h + (size_t)n * F + head * 32 + part * 8);
    float4 acc0 = hp[0], acc1 = hp[1];

    for (int i = beg; i < end; i++) {
        int s = g_col[i];
        float e = lrelu(g_as[s * HEADS + head] + adv);
        const float4* sp = (const float4*)(h + (size_t)s * F + head * 32 + part * 8);
        float4 s0 = sp[0], s1 = sp[1];
        if (e > m) {
            float r = __expf(m - e);
            denom = fmaf(denom, r, 1.f);
            acc0.x = fmaf(acc0.x, r, s0.x); acc0.y = fmaf(acc0.y, r, s0.y);
            acc0.z = fmaf(acc0.z, r, s0.z); acc0.w = fmaf(acc0.w, r, s0.w);
            acc1.x = fmaf(acc1.x, r, s1.x); acc1.y = fmaf(acc1.y, r, s1.y);
            acc1.z = fmaf(acc1.z, r, s1.z); acc1.w = fmaf(acc1.w, r, s1.w);
            m = e;
        } else {
            float ww = __expf(e - m);
            denom += ww;
            acc0.x = fmaf(ww, s0.x, acc0.x); acc0.y = fmaf(ww, s0.y, acc0.y);
            acc0.z = fmaf(ww, s0.z, acc0.z); acc0.w = fmaf(ww, s0.w, acc0.w);
            acc1.x = fmaf(ww, s1.x, acc1.x); acc1.y = fmaf(ww, s1.y, acc1.y);
            acc1.z = fmaf(ww, s1.z, acc1.z); acc1.w = fmaf(ww, s1.w, acc1.w);
        }
    }
    float inv = 1.f / denom;
    const float4* bp = (const float4*)(bias + head * 32 + part * 8);
    float4 b0 = bp[0], b1 = bp[1];
    float o[8];
    o[0] = fmaxf(fmaf(acc0.x, inv, b0.x), 0.f);
    o[1] = fmaxf(fmaf(acc0.y, inv, b0.y), 0.f);
    o[2] = fmaxf(fmaf(acc0.z, inv, b0.z), 0.f);
    o[3] = fmaxf(fmaf(acc0.w, inv, b0.w), 0.f);
    o[4] = fmaxf(fmaf(acc1.x, inv, b1.x), 0.f);
    o[5] = fmaxf(fmaf(acc1.y, inv, b1.y), 0.f);
    o[6] = fmaxf(fmaf(acc1.z, inv, b1.z), 0.f);
    o[7] = fmaxf(fmaf(acc1.w, inv, b1.w), 0.f);

    // split-bf16 epilogue: hi = bf16(o), lo = bf16(o - hi)
    ushort4 hA, hB, lA, lB;
    {
        __nv_bfloat16 b;
        float f;
        b = __float2bfloat16_rn(o[0]); f = o[0] - __bfloat162float(b); hA.x = __bfloat16_as_ushort(b); lA.x = __bfloat16_as_ushort(__float2bfloat16_rn(f));
        b = __float2bfloat16_rn(o[1]); f = o[1] - __bfloat162float(b); hA.y = __bfloat16_as_ushort(b); lA.y = __bfloat16_as_ushort(__float2bfloat16_rn(f));
        b = __float2bfloat16_rn(o[2]); f = o[2] - __bfloat162float(b); hA.z = __bfloat16_as_ushort(b); lA.z = __bfloat16_as_ushort(__float2bfloat16_rn(f));
        b = __float2bfloat16_rn(o[3]); f = o[3] - __bfloat162float(b); hA.w = __bfloat16_as_ushort(b); lA.w = __bfloat16_as_ushort(__float2bfloat16_rn(f));
        b = __float2bfloat16_rn(o[4]); f = o[4] - __bfloat162float(b); hB.x = __bfloat16_as_ushort(b); lB.x = __bfloat16_as_ushort(__float2bfloat16_rn(f));
        b = __float2bfloat16_rn(o[5]); f = o[5] - __bfloat162float(b); hB.y = __bfloat16_as_ushort(b); lB.y = __bfloat16_as_ushort(__float2bfloat16_rn(f));
        b = __float2bfloat16_rn(o[6]); f = o[6] - __bfloat162float(b); hB.z = __bfloat16_as_ushort(b); lB.z = __bfloat16_as_ushort(__float2bfloat16_rn(f));
        b = __float2bfloat16_rn(o[7]); f = o[7] - __bfloat162float(b); hB.w = __bfloat16_as_ushort(b); lB.w = __bfloat16_as_ushort(__float2bfloat16_rn(f));
    }
    size_t off = (size_t)n * 256 + head * 32 + part * 8;
    *(ushort4*)(g_Ah + off)     = hA;
    *(ushort4*)(g_Ah + off + 4) = hB;
    *(ushort4*)(g_Al + off)     = lA;
    *(ushort4*)(g_Al + off + 4) = lB;
}

// ---------------- edge predictor: 2 edges per thread ----------------
__global__ __launch_bounds__(128) void k_pred(const int* __restrict__ EI,
                                              const float* __restrict__ EA,
                                              const float* __restrict__ Wm1,
                                              const float* __restrict__ bm1,
                                              const float* __restrict__ Wm2,
                                              const float* __restrict__ bm2,
                                              const float* __restrict__ Wp1,
                                              const float* __restrict__ bp1,
                                              const float* __restrict__ Wp2,
                                              const float* __restrict__ bp2,
                                              float* __restrict__ OUT) {
    __shared__ float sW[3 * 1024];
    __shared__ float sB[3 * 32];
    __shared__ float sWp2[32];
    __shared__ float sbp2;

    int tid = threadIdx.x;
    for (int i = tid; i < 1024; i += 128) {
        sW[i]        = Wm1[i];
        sW[1024 + i] = Wm2[i];
        sW[2048 + i] = Wp1[512 * 32 + i];
    }
    if (tid < 32) {
        sB[tid]      = bm1[tid];
        sB[32 + tid] = bm2[tid];
        sB[64 + tid] = bp1[tid];
        sWp2[tid]    = Wp2[tid];
    }
    if (tid == 0) sbp2 = bp2[0];
    __syncthreads();

    int e0 = blockIdx.x * 256 + tid;
    int e1 = e0 + 128;
    if (e0 >= NE) return;
    bool has1 = (e1 < NE);
    int e1c = has1 ? e1 : e0;

    int r0 = EI[e0], c0 = EI[NE + e0];
    int r1 = EI[e1c], c1 = EI[NE + e1c];

    float in0[32], in1[32];
    {
        const float4* p0 = (const float4*)(EA + (size_t)e0 * 32);
        const float4* p1 = (const float4*)(EA + (size_t)e1c * 32);
        #pragma unroll
        for (int q = 0; q < 8; q++) {
            float4 v = p0[q];
            in0[q * 4 + 0] = v.x; in0[q * 4 + 1] = v.y;
            in0[q * 4 + 2] = v.z; in0[q * 4 + 3] = v.w;
            float4 u = p1[q];
            in1[q * 4 + 0] = u.x; in1[q * 4 + 1] = u.y;
            in1[q * 4 + 2] = u.z; in1[q * 4 + 3] = u.w;
        }
    }

    const float4* pa0 = (const float4*)(g_P + (size_t)r0 * 64);
    const float4* pb0 = (const float4*)(g_P + (size_t)c0 * 64 + 32);
    const float4* pa1 = (const float4*)(g_P + (size_t)r1 * 64);
    const float4* pb1 = (const float4*)(g_P + (size_t)c1 * 64 + 32);

    #pragma unroll 1
    for (int L = 0; L < 3; L++) {
        const float4* w4 = (const float4*)(sW + L * 1024);
        const float4* b4 = (const float4*)(sB + L * 32);
        float4 a0[8], a1[8];
        #pragma unroll
        for (int j = 0; j < 8; j++) { a0[j] = b4[j]; a1[j] = b4[j]; }
        if (L == 2) {
            #pragma unroll
            for (int j = 0; j < 8; j++) {
                float4 x = pa0[j], y = pb0[j];
                a0[j].x += x.x + y.x; a0[j].y += x.y + y.y;
                a0[j].z += x.z + y.z; a0[j].w += x.w + y.w;
                float4 u = pa1[j], v = pb1[j];
                a1[j].x += u.x + v.x; a1[j].y += u.y + v.y;
                a1[j].z += u.z + v.z; a1[j].w += u.w + v.w;
            }
        }
        #pragma unroll
        for (int k = 0; k < 32; k++) {
            float v0 = in0[k], v1 = in1[k];
            #pragma unroll
            for (int j = 0; j < 8; j++) {
                float4 w = w4[k * 8 + j];
                a0[j].x = fmaf(v0, w.x, a0[j].x);
                a0[j].y = fmaf(v0, w.y, a0[j].y);
                a0[j].z = fmaf(v0, w.z, a0[j].z);
                a0[j].w = fmaf(v0, w.w, a0[j].w);
                a1[j].x = fmaf(v1, w.x, a1[j].x);
                a1[j].y = fmaf(v1, w.y, a1[j].y);
                a1[j].z = fmaf(v1, w.z, a1[j].z);
                a1[j].w = fmaf(v1, w.w, a1[j].w);
            }
        }
        #pragma unroll
        for (int j = 0; j < 8; j++) {
            in0[j * 4 + 0] = fmaxf(a0[j].x, 0.f);
            in0[j * 4 + 1] = fmaxf(a0[j].y, 0.f);
            in0[j * 4 + 2] = fmaxf(a0[j].z, 0.f);
            in0[j * 4 + 3] = fmaxf(a0[j].w, 0.f);
            in1[j * 4 + 0] = fmaxf(a1[j].x, 0.f);
            in1[j * 4 + 1] = fmaxf(a1[j].y, 0.f);
            in1[j * 4 + 2] = fmaxf(a1[j].z, 0.f);
            in1[j * 4 + 3] = fmaxf(a1[j].w, 0.f);
        }
    }

    float s0 = sbp2, s1 = sbp2;
    #pragma unroll
    for (int j = 0; j < 32; j++) {
        float w = sWp2[j];
        s0 = fmaf(in0[j], w, s0);
        s1 = fmaf(in1[j], w, s1);
    }
    OUT[e0] = s0;
    if (has1) OUT[e1] = s1;
}

// ---------------- launch ----------------
extern "C" void kernel_launch(void* const* d_in, const int* in_sizes, int n_in,
                              void* d_out, int out_size) {
    const float* x    = (const float*)d_in[0];
    const int*   ei   = (const int*)d_in[1];
    const float* ea   = (const float*)d_in[2];
    const float* W1   = (const float*)d_in[3];
    const float* as1  = (const float*)d_in[4];
    const float* ad1  = (const float*)d_in[5];
    const float* b1   = (const float*)d_in[6];
    const float* W2   = (const float*)d_in[7];
    const float* as2  = (const float*)d_in[8];
    const float* ad2  = (const float*)d_in[9];
    const float* b2   = (const float*)d_in[10];
    const float* Wm1  = (const float*)d_in[11];
    const float* bm1  = (const float*)d_in[12];
    const float* Wm2  = (const float*)d_in[13];
    const float* bm2  = (const float*)d_in[14];
    const float* Wp1  = (const float*)d_in[15];
    const float* bp1  = (const float*)d_in[16];
    const float* Wp2  = (const float*)d_in[17];
    const float* bp2  = (const float*)d_in[18];
    float* out = (float*)d_out;

    float *ph, *pP;
    __nv_bfloat16 *pAh, *pAl, *pBh, *pBl;
    cudaGetSymbolAddress((void**)&ph,  g_h);
    cudaGetSymbolAddress((void**)&pP,  g_P);
    cudaGetSymbolAddress((void**)&pAh, g_Ah);
    cudaGetSymbolAddress((void**)&pAl, g_Al);
    cudaGetSymbolAddress((void**)&pBh, g_Bh);
    cudaGetSymbolAddress((void**)&pBl, g_Bl);

    // CSR
    {
        int* degp; cudaGetSymbolAddress((void**)&degp, g_deg);
        k_zero<<<(NN + 255) / 256, 256>>>(degp, NN);
    }
    k_count<<<(NE + 255) / 256, 256>>>(ei);
    k_scan<<<1, 1024>>>();
    k_fill<<<(NE + 255) / 256, 256>>>(ei);

    int nwBlocks = (NN * 32 + 255) / 256;
    int tilesM = MPAD / 128;   // 391

    // ---- layer 1:  h = x @ W1 ----
    k_splitW<<<(256 * NODE_IN + 255) / 256, 256>>>(W1, NODE_IN, F);
    {
        int t4 = NN * NODE_IN / 4;
        k_splitA<<<(t4 + 255) / 256, 256>>>(x, t4);
    }
    k_mma<<<dim3(2, tilesM), 256>>>(pAh, pAl, pBh, pBl, ph, NN, F, NODE_IN, F);
    k_attn<<<nwBlocks, 256>>>(ph, as1, ad1);
    k_agg<<<nwBlocks, 256>>>(ph, b1);   // writes g_Ah/g_Al (layer-2 A operand)

    // ---- layer 2:  h = x @ W2 ----
    k_splitW<<<(256 * 256 + 255) / 256, 256>>>(W2, F, F);
    k_mma<<<dim3(2, tilesM), 256>>>(pAh, pAl, pBh, pBl, ph, NN, F, F, F);
    k_attn<<<nwBlocks, 256>>>(ph, as2, ad2);
    k_agg<<<nwBlocks, 256>>>(ph, b2);   // writes g_Ah/g_Al (P-GEMM A operand)

    // ---- node-side predictor partials: P = x @ [Wp1_a | Wp1_b] ----
    k_splitWp<<<(128 * 256 + 255) / 256, 256>>>(Wp1);
    k_mma<<<dim3(1, tilesM), 256>>>(pAh, pAl, pBh, pBl, pP, NN, 64, F, 64);

    // ---- edge predictor ----
    k_pred<<<(NE + 255) / 256, 128>>>(ei, ea, Wm1, bm1, Wm2, bm2,
                                      Wp1, bp1, Wp2, bp2, out);
}